// round 12
// baseline (speedup 1.0000x reference)
#include <cuda_runtime.h>
#include <cuda_fp16.h>
#include <cstdint>

// Fixed problem: B=2048, S=64, H=256, n_steps=32
#define BB 2048
#define HH 256
#define SS 64
#define NSTEPS 32
#define N4 1024
#define PS ((NSTEPS+1)*HH)
#define THREADS 512
#define TOTAL (SS + NSTEPS)

#define TILE_B 16384                 // 128 rows x 64 fp16 cols, SW128 rows of 128B
#define W_BYTES (8*TILE_B)           // 128 KB resident: Whh tiles[0..3], Wc tiles[4..7]
#define AB_OFF  W_BYTES
#define ZS_OFF  (W_BYTES + 4*TILE_B)          // Z staging: 32 KB
#define MB_OFF  (ZS_OFF + THREADS*64)         // 4 mbarriers (32 B)
#define SMEM_BYTES (MB_OFF + 64)

// xw_gemm smem: Wih 4 tiles + 2 fp16 A bufs + 3 fp32 staging bufs
#define XW_A_OFF  (4*TILE_B)
#define XW_S_OFF  (6*TILE_B)
#define XSTAGE_B  32768
#define XW_SMEM   (6*TILE_B + 3*XSTAGE_B)   // 192 KB

// ---------------- static device scratch ------------------------------------
__device__ uint32_t g_h[2][BB*HH/2];      // packed fp16 pairs (unit j even/odd)
__device__ __half g_z[(size_t)SS*BB*N4];  // precomputed x@Wih^T, per-thread layout
__device__ __half g_Whh[N4*HH];
__device__ __half g_Wih[N4*HH];
__device__ __half g_Wc [N4*HH];
__device__ float g_bias[N4];

// ---------------- small helpers ---------------------------------------------
__device__ __forceinline__ uint32_t smem_u32(const void* p) {
    uint32_t a;
    asm("{ .reg .u64 t; cvta.to.shared.u64 t, %1; cvt.u32.u64 %0, t; }" : "=r"(a) : "l"(p));
    return a;
}
__device__ __forceinline__ uint32_t swz(uint32_t b) { return b ^ ((b >> 3) & 0x70u); }

__device__ __forceinline__ void cp16(uint32_t d, const void* s) {
    asm volatile("cp.async.cg.shared.global [%0], [%1], 16;" :: "r"(d), "l"(s) : "memory");
}
#define CP_COMMIT() asm volatile("cp.async.commit_group;" ::: "memory")
#define CP_WAITG(n) asm volatile("cp.async.wait_group %0;" :: "n"(n) : "memory")

#define MBARRIER_INIT(addr, cnt) \
    asm volatile("mbarrier.init.shared.b64 [%0], %1;" :: "r"(addr), "r"(cnt) : "memory")

// cluster-scope acquire wait on local mbarrier (phase parity)
#define MBAR_WAIT_CL(mbar_addr, phase_parity) do { \
    uint32_t _mbar = (uint32_t)(mbar_addr); \
    uint32_t _par  = (uint32_t)(phase_parity); \
    uint32_t _done; \
    asm volatile("{\n\t.reg .pred p;\n\t" \
        "mbarrier.try_wait.parity.acquire.cluster.shared::cta.b64 p, [%1], %2;\n\t" \
        "selp.b32 %0, 1, 0, p;\n\t}" : "=r"(_done) : "r"(_mbar), "r"(_par) : "memory"); \
    if (!_done) { \
        asm volatile("{\n\t.reg .pred P1;\n\t" \
            "WAIT_LOOP_%=:\n\t" \
            "mbarrier.try_wait.parity.acquire.cluster.shared::cta.b64 P1, [%0], %1, 0x989680;\n\t" \
            "@P1 bra.uni WAIT_DONE_%=;\n\t" \
            "bra.uni WAIT_LOOP_%=;\n\t" \
            "WAIT_DONE_%=:\n\t}" :: "r"(_mbar), "r"(_par) : "memory"); \
    } \
} while (0)

__device__ __forceinline__ void ldsm4(uint32_t& r0, uint32_t& r1, uint32_t& r2, uint32_t& r3,
                                      uint32_t a) {
    asm volatile("ldmatrix.sync.aligned.m8n8.x4.shared.b16 {%0,%1,%2,%3}, [%4];"
                 : "=r"(r0), "=r"(r1), "=r"(r2), "=r"(r3) : "r"(a));
}
// fp16-accumulator HMMA: D,C packed half2 x2
__device__ __forceinline__ void mma16816h(uint32_t* c, const uint32_t* a, const uint32_t* b) {
    asm volatile("mma.sync.aligned.m16n8k16.row.col.f16.f16.f16.f16 "
                 "{%0,%1}, {%2,%3,%4,%5}, {%6,%7}, {%0,%1};"
                 : "+r"(c[0]), "+r"(c[1])
                 : "r"(a[0]), "r"(a[1]), "r"(a[2]), "r"(a[3]), "r"(b[0]), "r"(b[1]));
}

// MUFU.TANH-based activations
__device__ __forceinline__ float tanh_fast(float x) {
    float y;
    asm("tanh.approx.f32 %0, %1;" : "=f"(y) : "f"(x));
    return y;
}
__device__ __forceinline__ float sig_fast(float x) {
    return fmaf(0.5f, tanh_fast(0.5f * x), 0.5f);
}

// ---------------- init kernel (weights only; 1024 CTAs) ----------------------
// Gate column permutation: col n -> gate=(n>>3)&3, unit j=(n>>7)*32+((n>>5)&3)*8+(n&7)
__global__ void init_weights(const float* __restrict__ W_ih, const float* __restrict__ W_hh,
                             const float* __restrict__ b_ih, const float* __restrict__ b_hh)
{
    int i = blockIdx.x * blockDim.x + threadIdx.x;     // 0 .. N4*HH-1 (= BB*HH/2)
    int n = i / HH, k = i % HH;
    int gate = (n >> 3) & 3;
    int j    = (n >> 7) * 32 + ((n >> 5) & 3) * 8 + (n & 7);
    int orig = gate * HH + j;
    float a = W_ih[orig * HH + k];
    float b = W_hh[orig * HH + k];
    g_Wih[i] = __float2half_rn(a);
    g_Whh[i] = __float2half_rn(b);
    g_Wc [i] = __float2half_rn(a + b);
    if (k == 0) g_bias[n] = b_ih[orig] + b_hh[orig];
    g_h[0][i] = 0u;                                    // N4*HH == BB*HH/2
}

// ---------------- per-chunk MMA body (warp tile 32M x 32N, fp16 acc) ---------
__device__ __forceinline__ void do_chunk(uint32_t acc[2][4][2], uint32_t ab, uint32_t wb,
                                         int wm, int wn, int lane)
{
    #pragma unroll
    for (int ks = 0; ks < 4; ks++) {
        uint32_t bf[4][2];
        {
            const int gsel = lane >> 3;                       // 0..3
            const int nloc = wn * 32 + (gsel >> 1) * 8 + (lane & 7);
            const int kb   = ks * 32 + (gsel & 1) * 16;
            uint32_t o01 = swz((uint32_t)nloc * 128u + kb);
            uint32_t o23 = swz((uint32_t)(nloc + 16) * 128u + kb);
            ldsm4(bf[0][0], bf[0][1], bf[1][0], bf[1][1], wb + o01);
            ldsm4(bf[2][0], bf[2][1], bf[3][0], bf[3][1], wb + o23);
        }
        #pragma unroll
        for (int mf = 0; mf < 2; mf++) {
            const int rloc = wm * 32 + mf * 16 + (lane & 15);
            const int kb   = ks * 32 + (lane >> 4) * 16;
            uint32_t ao = swz((uint32_t)rloc * 128u + kb);
            uint32_t ah[4];
            ldsm4(ah[0], ah[1], ah[2], ah[3], ab + ao);
            #pragma unroll
            for (int g = 0; g < 4; g++) mma16816h(acc[mf][g], ah, bf[g]);
        }
    }
}

// ---------------- parallel pre-GEMM: Z[t] = x_t @ Wih^T (reads fp32 x0) ------
// Grid (8, 16, 8): CTA computes (bn, bm) tile for t = bz*8 .. bz*8+7.
__global__ void __launch_bounds__(THREADS, 1)
xw_gemm(const float* __restrict__ x0)
{
    extern __shared__ char smem[];
    const uint32_t sb = smem_u32(smem);
    const int tid  = threadIdx.x;
    const int wid  = tid >> 5, lane = tid & 31;
    const int bn   = blockIdx.x, bm = blockIdx.y, bz = blockIdx.z;
    const int wm   = wid >> 2, wn = wid & 3;

    // Wih tiles [0..3] resident
    #pragma unroll
    for (int i = 0; i < 8; i++) {
        int tl = i >> 1;
        int id = tid + (i & 1) * THREADS;
        int r  = id >> 3, cb = id & 7;
        uint32_t so = swz((uint32_t)r * 128u + (uint32_t)cb * 16u);
        cp16(sb + tl * TILE_B + so, g_Wih + (size_t)(bn * 128 + r) * HH + (tl & 3) * 64 + cb * 8);
    }

    auto stage_load = [&](int q) {        // fp32 x chunk -> staging (q%3), linear
        const int t  = bz * 8 + (q >> 2);
        const int kc = (q & 3) * 64;
        const uint32_t st = sb + XW_S_OFF + (q % 3) * XSTAGE_B;
        #pragma unroll
        for (int i = 0; i < 4; i++) {
            int id = tid + i * THREADS;               // 0..2047
            int r  = id >> 4, cf = id & 15;           // row, 4-float chunk
            cp16(st + (uint32_t)id * 16u,
                 x0 + ((size_t)(bm * 128 + r) * SS + t) * HH + kc + cf * 4);
        }
    };

    stage_load(0); CP_COMMIT();
    stage_load(1); CP_COMMIT();

    uint32_t acc[2][4][2];
    for (int q = 0; q < 32; q++) {
        CP_WAITG(1);
        __syncthreads();
        if (q + 2 < 32) { stage_load(q + 2); CP_COMMIT(); }

        // convert staging (q%3) fp32 -> A fp16 buf (q%2), SW128 swizzled
        {
            const char* st = smem + XW_S_OFF + (q % 3) * XSTAGE_B;
            const uint32_t ad = sb + XW_A_OFF + (q % 2) * TILE_B;
            #pragma unroll
            for (int i = 0; i < 2; i++) {
                int id = tid + i * THREADS;           // 0..1023
                int r  = id >> 3, cb = id & 7;
                float4 f0 = *(const float4*)(st + (size_t)id * 32);
                float4 f1 = *(const float4*)(st + (size_t)id * 32 + 16);
                uint4 v;
                __half2* hp = reinterpret_cast<__half2*>(&v);
                hp[0] = __floats2half2_rn(f0.x, f0.y);
                hp[1] = __floats2half2_rn(f0.z, f0.w);
                hp[2] = __floats2half2_rn(f1.x, f1.y);
                hp[3] = __floats2half2_rn(f1.z, f1.w);
                uint32_t so = swz((uint32_t)r * 128u + (uint32_t)cb * 16u);
                *(uint4*)(smem + (ad - sb) + so) = v;
            }
        }
        __syncthreads();

        if ((q & 3) == 0) {
            #pragma unroll
            for (int a = 0; a < 2; a++)
                #pragma unroll
                for (int b = 0; b < 4; b++) { acc[a][b][0] = 0u; acc[a][b][1] = 0u; }
        }
        do_chunk(acc, sb + XW_A_OFF + (q % 2) * TILE_B, sb + (q & 3) * TILE_B,
                 wm, wn, lane);

        if ((q & 3) == 3) {
            const int t = bz * 8 + (q >> 2);
            uint4* zp = reinterpret_cast<uint4*>(
                g_z + ((((size_t)t * 16 + bm) * 8 + bn) * THREADS + tid) * 32);
            #pragma unroll
            for (int u = 0; u < 4; u++) {            // u = mf*2+rr
                const int mf = u >> 1, rr = u & 1;
                uint4 v;
                v.x = acc[mf][0][rr]; v.y = acc[mf][1][rr];
                v.z = acc[mf][2][rr]; v.w = acc[mf][3][rr];
                zp[u] = v;
            }
        }
    }
}

// ---------------- persistent fused LSTM kernel ------------------------------
// Fine-grained cross-CTA dataflow (see round 11 notes): 4 mbarriers/CTA, one
// per producer pair; producers release-arrive on all cluster CTAs after their
// h-stores; consumers acquire-wait right before issuing chunk-c loads.
__global__ void __launch_bounds__(THREADS, 1) __cluster_dims__(8, 1, 1)
lstm_persist(float* __restrict__ out)
{
    extern __shared__ char smem[];
    const uint32_t sb = smem_u32(smem);
    const int tid  = threadIdx.x;
    const int wid  = tid >> 5, lane = tid & 31;
    const int bn   = blockIdx.x;          // 0..7 (cluster rank)
    const int bm   = blockIdx.y;          // 0..15
    const int wm   = wid >> 2, wn = wid & 3;   // 4x4 warp grid: 32M x 32N tiles

    // init mbarriers, then one-time cluster sync so inits are visible
    if (tid < 4) MBARRIER_INIT(sb + MB_OFF + tid * 8, 2);
    asm volatile("barrier.cluster.arrive.aligned;" ::: "memory");
    asm volatile("barrier.cluster.wait.aligned;"   ::: "memory");

    float bias_r[4][2];
    #pragma unroll
    for (int g = 0; g < 4; g++)
        #pragma unroll
        for (int qq = 0; qq < 2; qq++)
            bias_r[g][qq] = g_bias[bn * 128 + wn * 32 + g * 8 + (lane & 3) * 2 + qq];

    float creg[8];
    #pragma unroll
    for (int i = 0; i < 8; i++) creg[i] = 0.0f;

    int sel = 0;

    for (int step = 0; step < TOTAL; step++) {
        const bool enc = (step < SS);
        const uint32_t par = (uint32_t)(step - 1) & 1u;   // phase parity for waits (step>0)

        uint32_t acc[2][4][2];
        #pragma unroll
        for (int a = 0; a < 2; a++)
            #pragma unroll
            for (int b = 0; b < 4; b++) { acc[a][b][0] = 0u; acc[a][b][1] = 0u; }

        // ---- warp-local A-chunk loader: this warp's 32 rows, full chunk ----
        auto load_a_warp = [&](int c) {
            const uint32_t ab = sb + AB_OFF + c * TILE_B;
            const __half* hh_ = (const __half*)g_h[sel];
            const int kc = c * 64;
            #pragma unroll
            for (int i = 0; i < 8; i++) {
                int id = i * 32 + lane;                // 0..255
                int r  = wm * 32 + (id >> 3);          // rows wm*32 .. wm*32+31
                int cb = id & 7;
                uint32_t so = swz((uint32_t)r * 128u + (uint32_t)cb * 16u);
                cp16(ab + so, hh_ + (size_t)(bm * 128 + r) * HH + kc + cb * 8);
            }
        };

        // One-time W loads (CTA-wide): Whh -> tiles[0..3], Wc -> tiles[4..7]
        if (step == 0) {
            #pragma unroll
            for (int i = 0; i < 16; i++) {
                int tl = i >> 1;                       // tile 0..7
                int id = tid + (i & 1) * THREADS;
                int r  = id >> 3, cb = id & 7;
                const __half* w = (tl < 4) ? g_Whh : g_Wc;
                int kc = (tl & 3) * 64;
                uint32_t so = swz((uint32_t)r * 128u + (uint32_t)cb * 16u);
                cp16(sb + tl * TILE_B + so, w + (size_t)(bn * 128 + r) * HH + kc + cb * 8);
            }
            CP_COMMIT();                               // W = its own (oldest) group
        }
        // ENC: prefetch this step's Z tile (own 64 B per thread, read by the
        // same thread after the chunk loop — no CTA sync needed). Rides group A0.
        if (enc) {
            const __half* zsrc = g_z + ((((size_t)step * 16 + bm) * 8 + bn) * THREADS + tid) * 32;
            const uint32_t zd = sb + ZS_OFF + (uint32_t)tid * 64u;
            cp16(zd,      zsrc);
            cp16(zd + 16, zsrc + 8);
            cp16(zd + 32, zsrc + 16);
            cp16(zd + 48, zsrc + 24);
        }

        const uint32_t wbase = sb + (enc ? 0 : 4 * TILE_B);

        // chunk-paced loads with per-pair mbarrier waits (step 0: h pre-zeroed)
        if (step) MBAR_WAIT_CL(sb + MB_OFF + 0, par);
        load_a_warp(0); CP_COMMIT();
        if (step) MBAR_WAIT_CL(sb + MB_OFF + 8, par);
        load_a_warp(1); CP_COMMIT();
        if (step == 0) { CP_WAITG(2); __syncthreads(); }   // W visible to all warps

        CP_WAITG(1);
        do_chunk(acc, sb + AB_OFF + 0 * TILE_B, wbase + 0 * TILE_B, wm, wn, lane);
        if (step) MBAR_WAIT_CL(sb + MB_OFF + 16, par);
        load_a_warp(2); CP_COMMIT();

        CP_WAITG(1);
        do_chunk(acc, sb + AB_OFF + 1 * TILE_B, wbase + 1 * TILE_B, wm, wn, lane);
        if (step) MBAR_WAIT_CL(sb + MB_OFF + 24, par);
        load_a_warp(3); CP_COMMIT();

        CP_WAITG(1);
        do_chunk(acc, sb + AB_OFF + 2 * TILE_B, wbase + 2 * TILE_B, wm, wn, lane);
        CP_WAITG(0);
        do_chunk(acc, sb + AB_OFF + 3 * TILE_B, wbase + 3 * TILE_B, wm, wn, lane);

        // ---- fold in precomputed x@Wih (ENC only): fp16x2 adds ----
        if (enc) {
            #pragma unroll
            for (int u = 0; u < 4; u++) {            // u = mf*2+rr
                const int mf = u >> 1, rr = u & 1;
                uint4 v = *(const uint4*)(smem + ZS_OFF + (size_t)tid * 64 + u * 16);
                const uint32_t* hp = reinterpret_cast<const uint32_t*>(&v);
                #pragma unroll
                for (int g = 0; g < 4; g++) {
                    __half2 s = __hadd2(*reinterpret_cast<__half2*>(&acc[mf][g][rr]),
                                        *reinterpret_cast<const __half2*>(&hp[g]));
                    acc[mf][g][rr] = *reinterpret_cast<uint32_t*>(&s);
                }
            }
        }

        // ---- fused LSTM epilogue (unpack fp16 acc; MUFU.TANH activations) ----
        const int  slot   = enc ? 0 : (step - SS + 1);
        const bool wrpred = (!enc) || (step == SS - 1);
        uint32_t* hout = g_h[sel ^ 1];

        float hv_all[8];
        #pragma unroll
        for (int mf = 0; mf < 2; mf++) {
            #pragma unroll
            for (int rr = 0; rr < 2; rr++) {
                float2 gx[4];
                #pragma unroll
                for (int g = 0; g < 4; g++)
                    gx[g] = __half22float2(*reinterpret_cast<__half2*>(&acc[mf][g][rr]));
                float hv[2];
                #pragma unroll
                for (int qq = 0; qq < 2; qq++) {
                    float iv = sig_fast ((qq ? gx[0].y : gx[0].x) + bias_r[0][qq]);
                    float fv = sig_fast ((qq ? gx[1].y : gx[1].x) + bias_r[1][qq]);
                    float gv = tanh_fast((qq ? gx[2].y : gx[2].x) + bias_r[2][qq]);
                    float ov = sig_fast ((qq ? gx[3].y : gx[3].x) + bias_r[3][qq]);
                    const int ci = mf * 4 + rr * 2 + qq;
                    creg[ci] = fmaf(fv, creg[ci], iv * gv);
                    hv[qq] = ov * tanh_fast(creg[ci]);
                    hv_all[ci] = hv[qq];
                }
                const int row = bm * 128 + wm * 32 + mf * 16 + (lane >> 2) + rr * 8;
                const int j   = bn * 32 + wn * 8 + (lane & 3) * 2;
                __half2 hp = __floats2half2_rn(hv[0], hv[1]);
                hout[row * (HH / 2) + (j >> 1)] = *reinterpret_cast<uint32_t*>(&hp);
            }
        }

        // publish h: CTA-local join of h-stores, then release-arrive on
        // mbar[bn/2] of every cluster CTA. Skipped on the last step.
        if (step < TOTAL - 1) {
            __syncthreads();
            if (tid < 8) {
                uint32_t local = sb + MB_OFF + (bn >> 1) * 8;
                uint32_t remote;
                asm volatile("mapa.shared::cluster.u32 %0, %1, %2;"
                             : "=r"(remote) : "r"(local), "r"(tid));
                asm volatile("mbarrier.arrive.release.cluster.shared::cluster.b64 _, [%0];"
                             :: "r"(remote) : "memory");
            }
        }
        // pred stores off the critical path
        if (wrpred) {
            #pragma unroll
            for (int mf = 0; mf < 2; mf++)
                #pragma unroll
                for (int rr = 0; rr < 2; rr++) {
                    const int row = bm * 128 + wm * 32 + mf * 16 + (lane >> 2) + rr * 8;
                    const int j   = bn * 32 + wn * 8 + (lane & 3) * 2;
                    float2 p = make_float2(hv_all[mf * 4 + rr * 2 + 0],
                                           hv_all[mf * 4 + rr * 2 + 1]);
                    *(float2*)&out[(size_t)row * PS + (size_t)slot * HH + j] = p;
                }
        }
        sel ^= 1;
    }
}

// ---------------- launch ------------------------------------------------------
extern "C" void kernel_launch(void* const* d_in, const int* in_sizes, int n_in,
                              void* d_out, int out_size)
{
    const float* x0   = (const float*)d_in[0];
    const float* W_ih = (const float*)d_in[1];
    const float* W_hh = (const float*)d_in[2];
    const float* b_ih = (const float*)d_in[3];
    const float* b_hh = (const float*)d_in[4];
    float* out = (float*)d_out;
    (void)in_sizes; (void)n_in; (void)out_size;

    cudaFuncSetAttribute(lstm_persist,
                         cudaFuncAttributeMaxDynamicSharedMemorySize, SMEM_BYTES);
    cudaFuncSetAttribute(xw_gemm,
                         cudaFuncAttributeMaxDynamicSharedMemorySize, XW_SMEM);

    init_weights<<<N4 * HH / 256, 256>>>(W_ih, W_hh, b_ih, b_hh);

    dim3 xgrid(8, 16, 8);   // 1024 CTAs
    xw_gemm<<<xgrid, THREADS, XW_SMEM>>>(x0);

    dim3 grid(8, 16);       // 128 CTAs = 16 clusters of 8 (one cluster per bm group)
    lstm_persist<<<grid, THREADS, SMEM_BYTES>>>(out);
}

// round 13
// speedup vs baseline: 1.0170x; 1.0170x over previous
#include <cuda_runtime.h>
#include <cuda_fp16.h>
#include <cstdint>

// Fixed problem: B=2048, S=64, H=256, n_steps=32
#define BB 2048
#define HH 256
#define SS 64
#define NSTEPS 32
#define N4 1024
#define PS ((NSTEPS+1)*HH)
#define THREADS 512
#define TOTAL (SS + NSTEPS)

#define TILE_B 16384                 // 128 rows x 64 fp16 cols, SW128 rows of 128B
#define W_BYTES (8*TILE_B)           // 128 KB resident: Whh tiles[0..3], Wc tiles[4..7]
#define AB_OFF  W_BYTES
#define ZS_OFF  (W_BYTES + 4*TILE_B)          // Z staging: 32 KB
#define MB_OFF  (ZS_OFF + THREADS*64)         // 4 mbarriers (32 B)
#define SMEM_BYTES (MB_OFF + 64)

// xw_gemm smem: Wih 4 tiles + 2 fp16 A bufs + 3 fp32 staging bufs
#define XW_A_OFF  (4*TILE_B)
#define XW_S_OFF  (6*TILE_B)
#define XSTAGE_B  32768
#define XW_SMEM   (6*TILE_B + 3*XSTAGE_B)   // 192 KB

// ---------------- static device scratch ------------------------------------
__device__ uint32_t g_h[2][BB*HH/2];      // packed fp16 pairs (unit j even/odd)
__device__ __half g_z[(size_t)SS*BB*N4];  // precomputed x@Wih^T, per-thread layout
__device__ __half g_Whh[N4*HH];
__device__ __half g_Wih[N4*HH];
__device__ __half g_Wc [N4*HH];
__device__ float g_bias[N4];

// ---------------- small helpers ---------------------------------------------
__device__ __forceinline__ uint32_t smem_u32(const void* p) {
    uint32_t a;
    asm("{ .reg .u64 t; cvta.to.shared.u64 t, %1; cvt.u32.u64 %0, t; }" : "=r"(a) : "l"(p));
    return a;
}
__device__ __forceinline__ uint32_t swz(uint32_t b) { return b ^ ((b >> 3) & 0x70u); }

__device__ __forceinline__ void cp16(uint32_t d, const void* s) {
    asm volatile("cp.async.cg.shared.global [%0], [%1], 16;" :: "r"(d), "l"(s) : "memory");
}
#define CP_COMMIT() asm volatile("cp.async.commit_group;" ::: "memory")
#define CP_WAITG(n) asm volatile("cp.async.wait_group %0;" :: "n"(n) : "memory")

#define MBARRIER_INIT(addr, cnt) \
    asm volatile("mbarrier.init.shared.b64 [%0], %1;" :: "r"(addr), "r"(cnt) : "memory")

// cluster-scope acquire wait on local mbarrier (phase parity)
#define MBAR_WAIT_CL(mbar_addr, phase_parity) do { \
    uint32_t _mbar = (uint32_t)(mbar_addr); \
    uint32_t _par  = (uint32_t)(phase_parity); \
    uint32_t _done; \
    asm volatile("{\n\t.reg .pred p;\n\t" \
        "mbarrier.try_wait.parity.acquire.cluster.shared::cta.b64 p, [%1], %2;\n\t" \
        "selp.b32 %0, 1, 0, p;\n\t}" : "=r"(_done) : "r"(_mbar), "r"(_par) : "memory"); \
    if (!_done) { \
        asm volatile("{\n\t.reg .pred P1;\n\t" \
            "WAIT_LOOP_%=:\n\t" \
            "mbarrier.try_wait.parity.acquire.cluster.shared::cta.b64 P1, [%0], %1, 0x989680;\n\t" \
            "@P1 bra.uni WAIT_DONE_%=;\n\t" \
            "bra.uni WAIT_LOOP_%=;\n\t" \
            "WAIT_DONE_%=:\n\t}" :: "r"(_mbar), "r"(_par) : "memory"); \
    } \
} while (0)

__device__ __forceinline__ void ldsm4(uint32_t& r0, uint32_t& r1, uint32_t& r2, uint32_t& r3,
                                      uint32_t a) {
    asm volatile("ldmatrix.sync.aligned.m8n8.x4.shared.b16 {%0,%1,%2,%3}, [%4];"
                 : "=r"(r0), "=r"(r1), "=r"(r2), "=r"(r3) : "r"(a));
}
__device__ __forceinline__ void mma16816(float* c, const uint32_t* a, const uint32_t* b) {
    asm volatile("mma.sync.aligned.m16n8k16.row.col.f32.f16.f16.f32 "
                 "{%0,%1,%2,%3}, {%4,%5,%6,%7}, {%8,%9}, {%0,%1,%2,%3};"
                 : "+f"(c[0]), "+f"(c[1]), "+f"(c[2]), "+f"(c[3])
                 : "r"(a[0]), "r"(a[1]), "r"(a[2]), "r"(a[3]), "r"(b[0]), "r"(b[1]));
}

// MUFU.TANH-based activations
__device__ __forceinline__ float tanh_fast(float x) {
    float y;
    asm("tanh.approx.f32 %0, %1;" : "=f"(y) : "f"(x));
    return y;
}
__device__ __forceinline__ float sig_fast(float x) {
    return fmaf(0.5f, tanh_fast(0.5f * x), 0.5f);
}

// ---------------- init kernel (weights only; 1024 CTAs) ----------------------
// Gate column permutation: col n -> gate=(n>>3)&3, unit j=(n>>7)*32+((n>>5)&3)*8+(n&7)
__global__ void init_weights(const float* __restrict__ W_ih, const float* __restrict__ W_hh,
                             const float* __restrict__ b_ih, const float* __restrict__ b_hh)
{
    int i = blockIdx.x * blockDim.x + threadIdx.x;     // 0 .. N4*HH-1 (= BB*HH/2)
    int n = i / HH, k = i % HH;
    int gate = (n >> 3) & 3;
    int j    = (n >> 7) * 32 + ((n >> 5) & 3) * 8 + (n & 7);
    int orig = gate * HH + j;
    float a = W_ih[orig * HH + k];
    float b = W_hh[orig * HH + k];
    g_Wih[i] = __float2half_rn(a);
    g_Whh[i] = __float2half_rn(b);
    g_Wc [i] = __float2half_rn(a + b);
    if (k == 0) g_bias[n] = b_ih[orig] + b_hh[orig];
    g_h[0][i] = 0u;                                    // N4*HH == BB*HH/2
}

// ---------------- per-chunk MMA body (warp tile 32M x 32N, fp32 acc) ---------
__device__ __forceinline__ void do_chunk(float acc[2][4][4], uint32_t ab, uint32_t wb,
                                         int wm, int wn, int lane)
{
    #pragma unroll
    for (int ks = 0; ks < 4; ks++) {
        uint32_t bf[4][2];
        {
            const int gsel = lane >> 3;                       // 0..3
            const int nloc = wn * 32 + (gsel >> 1) * 8 + (lane & 7);
            const int kb   = ks * 32 + (gsel & 1) * 16;
            uint32_t o01 = swz((uint32_t)nloc * 128u + kb);
            uint32_t o23 = swz((uint32_t)(nloc + 16) * 128u + kb);
            ldsm4(bf[0][0], bf[0][1], bf[1][0], bf[1][1], wb + o01);
            ldsm4(bf[2][0], bf[2][1], bf[3][0], bf[3][1], wb + o23);
        }
        #pragma unroll
        for (int mf = 0; mf < 2; mf++) {
            const int rloc = wm * 32 + mf * 16 + (lane & 15);
            const int kb   = ks * 32 + (lane >> 4) * 16;
            uint32_t ao = swz((uint32_t)rloc * 128u + kb);
            uint32_t ah[4];
            ldsm4(ah[0], ah[1], ah[2], ah[3], ab + ao);
            #pragma unroll
            for (int g = 0; g < 4; g++) mma16816(acc[mf][g], ah, bf[g]);
        }
    }
}

// ---------------- parallel pre-GEMM: Z[t] = x_t @ Wih^T (reads fp32 x0) ------
// Grid (8, 16, 8): CTA computes (bn, bm) tile for t = bz*8 .. bz*8+7.
__global__ void __launch_bounds__(THREADS, 1)
xw_gemm(const float* __restrict__ x0)
{
    extern __shared__ char smem[];
    const uint32_t sb = smem_u32(smem);
    const int tid  = threadIdx.x;
    const int wid  = tid >> 5, lane = tid & 31;
    const int bn   = blockIdx.x, bm = blockIdx.y, bz = blockIdx.z;
    const int wm   = wid >> 2, wn = wid & 3;

    // Wih tiles [0..3] resident
    #pragma unroll
    for (int i = 0; i < 8; i++) {
        int tl = i >> 1;
        int id = tid + (i & 1) * THREADS;
        int r  = id >> 3, cb = id & 7;
        uint32_t so = swz((uint32_t)r * 128u + (uint32_t)cb * 16u);
        cp16(sb + tl * TILE_B + so, g_Wih + (size_t)(bn * 128 + r) * HH + (tl & 3) * 64 + cb * 8);
    }

    auto stage_load = [&](int q) {        // fp32 x chunk -> staging (q%3), linear
        const int t  = bz * 8 + (q >> 2);
        const int kc = (q & 3) * 64;
        const uint32_t st = sb + XW_S_OFF + (q % 3) * XSTAGE_B;
        #pragma unroll
        for (int i = 0; i < 4; i++) {
            int id = tid + i * THREADS;               // 0..2047
            int r  = id >> 4, cf = id & 15;           // row, 4-float chunk
            cp16(st + (uint32_t)id * 16u,
                 x0 + ((size_t)(bm * 128 + r) * SS + t) * HH + kc + cf * 4);
        }
    };

    stage_load(0); CP_COMMIT();
    stage_load(1); CP_COMMIT();

    float acc[2][4][4];
    for (int q = 0; q < 32; q++) {
        CP_WAITG(1);
        __syncthreads();
        if (q + 2 < 32) { stage_load(q + 2); CP_COMMIT(); }

        // convert staging (q%3) fp32 -> A fp16 buf (q%2), SW128 swizzled
        {
            const char* st = smem + XW_S_OFF + (q % 3) * XSTAGE_B;
            const uint32_t ad = sb + XW_A_OFF + (q % 2) * TILE_B;
            #pragma unroll
            for (int i = 0; i < 2; i++) {
                int id = tid + i * THREADS;           // 0..1023
                int r  = id >> 3, cb = id & 7;
                float4 f0 = *(const float4*)(st + (size_t)id * 32);
                float4 f1 = *(const float4*)(st + (size_t)id * 32 + 16);
                uint4 v;
                __half2* hp = reinterpret_cast<__half2*>(&v);
                hp[0] = __floats2half2_rn(f0.x, f0.y);
                hp[1] = __floats2half2_rn(f0.z, f0.w);
                hp[2] = __floats2half2_rn(f1.x, f1.y);
                hp[3] = __floats2half2_rn(f1.z, f1.w);
                uint32_t so = swz((uint32_t)r * 128u + (uint32_t)cb * 16u);
                *(uint4*)(smem + (ad - sb) + so) = v;
            }
        }
        __syncthreads();

        if ((q & 3) == 0) {
            #pragma unroll
            for (int a = 0; a < 2; a++)
                #pragma unroll
                for (int b = 0; b < 4; b++)
                    #pragma unroll
                    for (int r = 0; r < 4; r++) acc[a][b][r] = 0.0f;
        }
        do_chunk(acc, sb + XW_A_OFF + (q % 2) * TILE_B, sb + (q & 3) * TILE_B,
                 wm, wn, lane);

        if ((q & 3) == 3) {
            const int t = bz * 8 + (q >> 2);
            uint4* zp = reinterpret_cast<uint4*>(
                g_z + ((((size_t)t * 16 + bm) * 8 + bn) * THREADS + tid) * 32);
            #pragma unroll
            for (int u = 0; u < 4; u++) {            // u = mf*2+rr
                const int mf = u >> 1, rr = u & 1;
                uint4 v;
                __half2* hp = reinterpret_cast<__half2*>(&v);
                #pragma unroll
                for (int g = 0; g < 4; g++)
                    hp[g] = __floats2half2_rn(acc[mf][g][rr * 2 + 0], acc[mf][g][rr * 2 + 1]);
                zp[u] = v;
            }
        }
    }
}

// ---------------- persistent fused LSTM kernel ------------------------------
// Fine-grained cross-CTA dataflow: chunk c of step s needs h-units 64c..64c+63,
// produced only by cluster CTAs 2c, 2c+1. Each CTA hosts 4 mbarriers (count=2);
// producers arrive (release.cluster) on mbar[bn/2] of all 8 CTAs after their
// h-stores; consumers acquire-wait mbar[c] right before issuing chunk-c loads.
// Waits for later chunks hide under earlier chunks' MMAs. No cluster barrier
// in the steady state.
__global__ void __launch_bounds__(THREADS, 1) __cluster_dims__(8, 1, 1)
lstm_persist(float* __restrict__ out)
{
    extern __shared__ char smem[];
    const uint32_t sb = smem_u32(smem);
    const int tid  = threadIdx.x;
    const int wid  = tid >> 5, lane = tid & 31;
    const int bn   = blockIdx.x;          // 0..7 (cluster rank)
    const int bm   = blockIdx.y;          // 0..15
    const int wm   = wid >> 2, wn = wid & 3;   // 4x4 warp grid: 32M x 32N tiles

    // init mbarriers, then one-time cluster sync so inits are visible
    if (tid < 4) MBARRIER_INIT(sb + MB_OFF + tid * 8, 2);
    asm volatile("barrier.cluster.arrive.aligned;" ::: "memory");
    asm volatile("barrier.cluster.wait.aligned;"   ::: "memory");

    float bias_r[4][2];
    #pragma unroll
    for (int g = 0; g < 4; g++)
        #pragma unroll
        for (int qq = 0; qq < 2; qq++)
            bias_r[g][qq] = g_bias[bn * 128 + wn * 32 + g * 8 + (lane & 3) * 2 + qq];

    float creg[8];
    #pragma unroll
    for (int i = 0; i < 8; i++) creg[i] = 0.0f;

    int sel = 0;

    for (int step = 0; step < TOTAL; step++) {
        const bool enc = (step < SS);
        const uint32_t par = (uint32_t)(step - 1) & 1u;   // phase parity for waits (step>0)

        float acc[2][4][4];
        #pragma unroll
        for (int a = 0; a < 2; a++)
            #pragma unroll
            for (int b = 0; b < 4; b++)
                #pragma unroll
                for (int r = 0; r < 4; r++) acc[a][b][r] = 0.0f;

        // ---- warp-local A-chunk loader: this warp's 32 rows, full chunk ----
        auto load_a_warp = [&](int c) {
            const uint32_t ab = sb + AB_OFF + c * TILE_B;
            const __half* hh_ = (const __half*)g_h[sel];
            const int kc = c * 64;
            #pragma unroll
            for (int i = 0; i < 8; i++) {
                int id = i * 32 + lane;                // 0..255
                int r  = wm * 32 + (id >> 3);          // rows wm*32 .. wm*32+31
                int cb = id & 7;
                uint32_t so = swz((uint32_t)r * 128u + (uint32_t)cb * 16u);
                cp16(ab + so, hh_ + (size_t)(bm * 128 + r) * HH + kc + cb * 8);
            }
        };

        // One-time W loads (CTA-wide): Whh -> tiles[0..3], Wc -> tiles[4..7]
        if (step == 0) {
            #pragma unroll
            for (int i = 0; i < 16; i++) {
                int tl = i >> 1;                       // tile 0..7
                int id = tid + (i & 1) * THREADS;
                int r  = id >> 3, cb = id & 7;
                const __half* w = (tl < 4) ? g_Whh : g_Wc;
                int kc = (tl & 3) * 64;
                uint32_t so = swz((uint32_t)r * 128u + (uint32_t)cb * 16u);
                cp16(sb + tl * TILE_B + so, w + (size_t)(bn * 128 + r) * HH + kc + cb * 8);
            }
            CP_COMMIT();                               // W = its own (oldest) group
        }
        // ENC: prefetch this step's Z tile (own 64 B per thread, read by the
        // same thread after the chunk loop — no CTA sync needed). Rides group A0.
        if (enc) {
            const __half* zsrc = g_z + ((((size_t)step * 16 + bm) * 8 + bn) * THREADS + tid) * 32;
            const uint32_t zd = sb + ZS_OFF + (uint32_t)tid * 64u;
            cp16(zd,      zsrc);
            cp16(zd + 16, zsrc + 8);
            cp16(zd + 32, zsrc + 16);
            cp16(zd + 48, zsrc + 24);
        }

        const uint32_t wbase = sb + (enc ? 0 : 4 * TILE_B);

        // chunk-paced loads with per-pair mbarrier waits (step 0: h pre-zeroed)
        if (step) MBAR_WAIT_CL(sb + MB_OFF + 0, par);
        load_a_warp(0); CP_COMMIT();
        if (step) MBAR_WAIT_CL(sb + MB_OFF + 8, par);
        load_a_warp(1); CP_COMMIT();
        if (step == 0) { CP_WAITG(2); __syncthreads(); }   // W visible to all warps

        CP_WAITG(1);
        do_chunk(acc, sb + AB_OFF + 0 * TILE_B, wbase + 0 * TILE_B, wm, wn, lane);
        if (step) MBAR_WAIT_CL(sb + MB_OFF + 16, par);
        load_a_warp(2); CP_COMMIT();

        CP_WAITG(1);
        do_chunk(acc, sb + AB_OFF + 1 * TILE_B, wbase + 1 * TILE_B, wm, wn, lane);
        if (step) MBAR_WAIT_CL(sb + MB_OFF + 24, par);
        load_a_warp(3); CP_COMMIT();

        CP_WAITG(1);
        do_chunk(acc, sb + AB_OFF + 2 * TILE_B, wbase + 2 * TILE_B, wm, wn, lane);
        CP_WAITG(0);
        do_chunk(acc, sb + AB_OFF + 3 * TILE_B, wbase + 3 * TILE_B, wm, wn, lane);

        // ---- fused LSTM epilogue (Z fold inlined; MUFU.TANH activations) ----
        const int  slot   = enc ? 0 : (step - SS + 1);
        const bool wrpred = (!enc) || (step == SS - 1);
        uint32_t* hout = g_h[sel ^ 1];

        float hv_all[8];
        #pragma unroll
        for (int mf = 0; mf < 2; mf++) {
            #pragma unroll
            for (int rr = 0; rr < 2; rr++) {
                // gate pre-activations for this (mf, rr): acc + (Z if enc)
                float gx[4][2];
                if (enc) {
                    const int u = mf * 2 + rr;
                    uint4 v = *(const uint4*)(smem + ZS_OFF + (size_t)tid * 64 + u * 16);
                    const __half2* hp = reinterpret_cast<const __half2*>(&v);
                    #pragma unroll
                    for (int g = 0; g < 4; g++) {
                        float2 f = __half22float2(hp[g]);
                        gx[g][0] = acc[mf][g][rr * 2 + 0] + f.x;
                        gx[g][1] = acc[mf][g][rr * 2 + 1] + f.y;
                    }
                } else {
                    #pragma unroll
                    for (int g = 0; g < 4; g++) {
                        gx[g][0] = acc[mf][g][rr * 2 + 0];
                        gx[g][1] = acc[mf][g][rr * 2 + 1];
                    }
                }
                float hv[2];
                #pragma unroll
                for (int qq = 0; qq < 2; qq++) {
                    float iv = sig_fast (gx[0][qq] + bias_r[0][qq]);
                    float fv = sig_fast (gx[1][qq] + bias_r[1][qq]);
                    float gv = tanh_fast(gx[2][qq] + bias_r[2][qq]);
                    float ov = sig_fast (gx[3][qq] + bias_r[3][qq]);
                    const int ci = mf * 4 + rr * 2 + qq;
                    creg[ci] = fmaf(fv, creg[ci], iv * gv);
                    hv[qq] = ov * tanh_fast(creg[ci]);
                    hv_all[ci] = hv[qq];
                }
                const int row = bm * 128 + wm * 32 + mf * 16 + (lane >> 2) + rr * 8;
                const int j   = bn * 32 + wn * 8 + (lane & 3) * 2;
                __half2 hp = __floats2half2_rn(hv[0], hv[1]);
                hout[row * (HH / 2) + (j >> 1)] = *reinterpret_cast<uint32_t*>(&hp);
            }
        }

        // publish h: CTA-local join of h-stores, then release-arrive on
        // mbar[bn/2] of every cluster CTA. Skipped on the last step.
        if (step < TOTAL - 1) {
            __syncthreads();
            if (tid < 8) {
                uint32_t local = sb + MB_OFF + (bn >> 1) * 8;
                uint32_t remote;
                asm volatile("mapa.shared::cluster.u32 %0, %1, %2;"
                             : "=r"(remote) : "r"(local), "r"(tid));
                asm volatile("mbarrier.arrive.release.cluster.shared::cluster.b64 _, [%0];"
                             :: "r"(remote) : "memory");
            }
        }
        // pred stores off the critical path
        if (wrpred) {
            #pragma unroll
            for (int mf = 0; mf < 2; mf++)
                #pragma unroll
                for (int rr = 0; rr < 2; rr++) {
                    const int row = bm * 128 + wm * 32 + mf * 16 + (lane >> 2) + rr * 8;
                    const int j   = bn * 32 + wn * 8 + (lane & 3) * 2;
                    float2 p = make_float2(hv_all[mf * 4 + rr * 2 + 0],
                                           hv_all[mf * 4 + rr * 2 + 1]);
                    *(float2*)&out[(size_t)row * PS + (size_t)slot * HH + j] = p;
                }
        }
        sel ^= 1;
    }
}

// ---------------- launch ------------------------------------------------------
extern "C" void kernel_launch(void* const* d_in, const int* in_sizes, int n_in,
                              void* d_out, int out_size)
{
    const float* x0   = (const float*)d_in[0];
    const float* W_ih = (const float*)d_in[1];
    const float* W_hh = (const float*)d_in[2];
    const float* b_ih = (const float*)d_in[3];
    const float* b_hh = (const float*)d_in[4];
    float* out = (float*)d_out;
    (void)in_sizes; (void)n_in; (void)out_size;

    cudaFuncSetAttribute(lstm_persist,
                         cudaFuncAttributeMaxDynamicSharedMemorySize, SMEM_BYTES);
    cudaFuncSetAttribute(xw_gemm,
                         cudaFuncAttributeMaxDynamicSharedMemorySize, XW_SMEM);

    init_weights<<<N4 * HH / 256, 256>>>(W_ih, W_hh, b_ih, b_hh);

    dim3 xgrid(8, 16, 8);   // 1024 CTAs
    xw_gemm<<<xgrid, THREADS, XW_SMEM>>>(x0);

    dim3 grid(8, 16);       // 128 CTAs = 16 clusters of 8 (one cluster per bm group)
    lstm_persist<<<grid, THREADS, SMEM_BYTES>>>(out);
}